// round 17
// baseline (speedup 1.0000x reference)
#include <cuda_runtime.h>
#include <cuda_bf16.h>

#define NPTS   65536
#define MG     1024
#define KTOP   10
#define NTHR   128                  // 4 warps/block; 8 lanes per point
#define SEGS   8
#define PPB    (NTHR / SEGS)        // 16 points per block
#define NBLK   (NPTS / PPB)         // 4096 blocks
#define MSEG   (MG / SEGS)          // 128 gaussians per lane

// -0.5 * log2(e): exp(-0.5*quad) = 2^(LFAC*quad)
#define LFAC   (-0.72134752044448170367996234050095f)

__global__ __launch_bounds__(NTHR, 10)
void RendererTopK_32134945309178_kernel(const float* __restrict__ x,
                                        const float* __restrict__ mus,
                                        const float* __restrict__ covs,
                                        const float* __restrict__ cols,
                                        float* __restrict__ out)
{
    // Cholesky-factored gaussian params (5 floats each), broadcast LDS reads.
    // g = -(e1^2 + e2^2), e1 = u11*px + u12*py + o1, e2 = u22*py + o2,
    // where U^T U = 0.72135 * Sigma^{-1}, o = -U*mu. 5 FMA-ops per element.
    __shared__ float4 su[MG];        // {u11, u12, o1, u22}
    __shared__ float  so2[MG];       // o2

    for (int m = threadIdx.x; m < MG; m += NTHR) {
        float mx  = mus[2*m + 0];
        float my  = mus[2*m + 1];
        float c00 = covs[4*m + 0];
        float c01 = covs[4*m + 1];   // symmetric
        float c11 = covs[4*m + 3];
        float det = fmaf(c00, c11, -c01 * c01);
        float s   = (-LFAC) / det;                 // +0.72135/det
        float m00 = c11 * s, m01 = -c01 * s, m11 = c00 * s;
        float u11 = sqrtf(m00);
        float u12 = m01 / u11;
        float u22 = sqrtf(fmaf(-u12, u12, m11));   // SPD => positive
        float o1  = -fmaf(u11, mx, u12 * my);
        float o2  = -u22 * my;
        su[m]  = make_float4(u11, u12, o1, u22);
        so2[m] = o2;
    }
    __syncthreads();

    // 8 lanes per point. INTERLEAVED gaussian assignment m = 8*mm + seg:
    // the warp's 8 distinct float4 LDS addresses span 128 contiguous bytes
    // -> conflict-free broadcast.
    const int n   = blockIdx.x * PPB + (threadIdx.x >> 3);
    const int seg = threadIdx.x & 7;
    const float px = x[2*n + 0];
    const float py = x[2*n + 1];

    // ---- Pass A: branchless per-lane top-10 over 128 gaussians ----
    float q[KTOP];
#pragma unroll
    for (int i = 0; i < KTOP; i++) q[i] = -1e30f;

#pragma unroll 8
    for (int mm = 0; mm < MSEG; mm++) {
        const int m = (mm << 3) | seg;
        const float4 u  = su[m];
        const float  o2 = so2[m];
        const float e1 = fmaf(u.x, px, fmaf(u.y, py, u.z));
        const float e2 = fmaf(u.w, py, o2);
        const float t  = e2 * e2;
        const float v  = fmaf(e1, -e1, -t);        // g (log2-domain weight)
#pragma unroll
        for (int i = KTOP - 1; i >= 1; i--)
            q[i] = fminf(fmaxf(v, q[i]), q[i - 1]); // reads OLD q[i-1]
        q[0] = fmaxf(v, q[0]);
    }

    // ---- merge tree across the 8 lanes of each point ----
    // Full sorted merge identity (both inputs sorted desc, exact min/max,
    // symmetric in a<->b -> partner lanes get bit-identical results):
    //   r[i] = max(a[i], b[i], max_{j<i} min(a[j], b[i-1-j]))
    float b[KTOP], r[KTOP];

    // xor 1: full merge
#pragma unroll
    for (int i = 0; i < KTOP; i++)
        b[i] = __shfl_xor_sync(0xffffffffu, q[i], 1);
#pragma unroll
    for (int i = 0; i < KTOP; i++) {
        float t = fmaxf(q[i], b[i]);
#pragma unroll
        for (int j = 0; j < i; j++)
            t = fmaxf(t, fminf(q[j], b[i - 1 - j]));
        r[i] = t;
    }

    // xor 2: full merge
#pragma unroll
    for (int i = 0; i < KTOP; i++)
        b[i] = __shfl_xor_sync(0xffffffffu, r[i], 2);
#pragma unroll
    for (int i = 0; i < KTOP; i++) {
        float t = fmaxf(r[i], b[i]);
#pragma unroll
        for (int j = 0; j < i; j++)
            t = fmaxf(t, fminf(r[j], b[i - 1 - j]));
        q[i] = t;
    }

    // xor 4: only the 10th largest of the union is needed:
    //   thr = min_i max(a[i], b[9-i])   (bitonic top-k identity)
#pragma unroll
    for (int i = 0; i < KTOP; i++)
        b[i] = __shfl_xor_sync(0xffffffffu, q[i], 4);
    float thr = fmaxf(q[0], b[KTOP - 1]);
#pragma unroll
    for (int i = 1; i < KTOP; i++)
        thr = fminf(thr, fmaxf(q[i], b[KTOP - 1 - i]));

    // ---- Pass B: recompute g (identical expression -> identical bits),
    //      accumulate exp2(g)*color for the top-10 hits only ----
    float sum = 0.0f, cr = 0.0f, cg = 0.0f, cb = 0.0f;
#pragma unroll 4
    for (int mm = 0; mm < MSEG; mm++) {
        const int m = (mm << 3) | seg;
        const float4 u  = su[m];
        const float  o2 = so2[m];
        const float e1 = fmaf(u.x, px, fmaf(u.y, py, u.z));
        const float e2 = fmaf(u.w, py, o2);
        const float t  = e2 * e2;
        const float g  = fmaf(e1, -e1, -t);
        if (g >= thr) {
            float w;
            asm("ex2.approx.ftz.f32 %0, %1;" : "=f"(w) : "f"(g));
            sum += w;
            cr = fmaf(w, __ldg(&cols[3*m + 0]), cr);
            cg = fmaf(w, __ldg(&cols[3*m + 1]), cg);
            cb = fmaf(w, __ldg(&cols[3*m + 2]), cb);
        }
    }

    // reduce the 8 partial accumulators across the lane octet; seg 0 writes
    sum += __shfl_xor_sync(0xffffffffu, sum, 1);
    cr  += __shfl_xor_sync(0xffffffffu, cr, 1);
    cg  += __shfl_xor_sync(0xffffffffu, cg, 1);
    cb  += __shfl_xor_sync(0xffffffffu, cb, 1);
    sum += __shfl_xor_sync(0xffffffffu, sum, 2);
    cr  += __shfl_xor_sync(0xffffffffu, cr, 2);
    cg  += __shfl_xor_sync(0xffffffffu, cg, 2);
    cb  += __shfl_xor_sync(0xffffffffu, cb, 2);
    sum += __shfl_xor_sync(0xffffffffu, sum, 4);
    cr  += __shfl_xor_sync(0xffffffffu, cr, 4);
    cg  += __shfl_xor_sync(0xffffffffu, cg, 4);
    cb  += __shfl_xor_sync(0xffffffffu, cb, 4);

    if (seg == 0) {
        const float inv = 1.0f / (sum + 1e-6f);
        out[3*n + 0] = cr * inv;
        out[3*n + 1] = cg * inv;
        out[3*n + 2] = cb * inv;
    }
}

extern "C" void kernel_launch(void* const* d_in, const int* in_sizes, int n_in,
                              void* d_out, int out_size)
{
    // Resolve inputs by element count (robust to metadata ordering):
    //   x: 65536*2 = 131072, mus: 1024*2 = 2048, covs: 1024*4 = 4096, cols: 1024*3 = 3072
    const float* x    = nullptr;
    const float* mus  = nullptr;
    const float* covs = nullptr;
    const float* cols = nullptr;
    for (int i = 0; i < n_in; i++) {
        switch (in_sizes[i]) {
            case 131072: x    = (const float*)d_in[i]; break;
            case 2048:   mus  = (const float*)d_in[i]; break;
            case 4096:   covs = (const float*)d_in[i]; break;
            case 3072:   cols = (const float*)d_in[i]; break;
            default: break;
        }
    }
    RendererTopK_32134945309178_kernel<<<NBLK, NTHR>>>(x, mus, covs, cols,
                                                       (float*)d_out);
}